// round 16
// baseline (speedup 1.0000x reference)
#include <cuda_runtime.h>
#include <math.h>

// Problem constants
#define BB        4
#define NPTS      4096
#define MPTS      4096
#define TPB       768               // 24 warps, 6/SMSP, 85 regs/thread cap
#define SRCB      128               // sources per block
#define BLK_PER_B 32                // blocks per batch
#define NBLK      (BB * BLK_PER_B)  // 128 blocks total, 1 per SM
#define NPAIRS    (MPTS / 2)        // 2048 target pairs per batch
#define GP        32                // pairs per cell
#define NQG       64                // cells; cell t covers pairs [32t,32t+32)
#define ICP_STEPS 16
#define ICP_TOL   1e-6

// ---------------------------------------------------------------------------
// Device-global state. g_cnt monotonic within a launch, reset by the final
// block -> replay-clean for CUDA graphs. g_wsum double-buffered by parity.
// ---------------------------------------------------------------------------
__device__ float    g_wsum[2][BB][128][16];
__device__ unsigned g_cnt;

// ---------------------------------------------------------------------------
__device__ __forceinline__ void xform(const float* Mtx,
                                      float px, float py, float pz,
                                      float& qx, float& qy, float& qz) {
    qx = fmaf(Mtx[0], px, fmaf(Mtx[1], py, fmaf(Mtx[2], pz, Mtx[9])));
    qy = fmaf(Mtx[3], px, fmaf(Mtx[4], py, fmaf(Mtx[5], pz, Mtx[10])));
    qz = fmaf(Mtx[6], px, fmaf(Mtx[7], py, fmaf(Mtx[8], pz, Mtx[11])));
}

// packed f32x2 helpers (per-half rounding identical to scalar FFMA)
__device__ __forceinline__ unsigned long long pk2(float v) {
    unsigned long long r;
    asm("mov.b64 %0, {%1, %1};" : "=l"(r) : "f"(v));
    return r;
}
__device__ __forceinline__ unsigned long long fma2(unsigned long long a,
                                                   unsigned long long b,
                                                   unsigned long long c) {
    unsigned long long d;
    asm("fma.rn.f32x2 %0, %1, %2, %3;" : "=l"(d) : "l"(a), "l"(b), "l"(c));
    return d;
}
__device__ __forceinline__ void upk2(unsigned long long v, float& lo, float& hi) {
    asm("mov.b64 {%0, %1}, %2;" : "=f"(lo), "=f"(hi) : "l"(v));
}

// ---------------------------------------------------------------------------
// Kabsch from accumulated sums (identical arithmetic to R2-R15).
// ---------------------------------------------------------------------------
__device__ void kabsch_sums(const double* S, float* Rt) {
    const double invN = 1.0 / (double)NPTS;
    double cs[3] = { S[0] * invN, S[1] * invN, S[2] * invN };
    double ct[3] = { S[3] * invN, S[4] * invN, S[5] * invN };

    float H[3][3];
    for (int i = 0; i < 3; ++i)
        for (int j = 0; j < 3; ++j)
            H[i][j] = (float)(S[6 + 3 * i + j] - (double)NPTS * cs[i] * ct[j]);

    float A[3][3];
    for (int i = 0; i < 3; ++i)
        for (int j = 0; j < 3; ++j)
            A[i][j] = H[0][i] * H[0][j] + H[1][i] * H[1][j] + H[2][i] * H[2][j];

    float V[3][3] = { {1,0,0},{0,1,0},{0,0,1} };
    const float diagmag = fabsf(A[0][0]) + fabsf(A[1][1]) + fabsf(A[2][2]);
    const float offeps  = diagmag * 1e-9f;
    for (int sweep = 0; sweep < 8; ++sweep) {
        const float off = fabsf(A[0][1]) + fabsf(A[0][2]) + fabsf(A[1][2]);
        if (off <= offeps) break;
        for (int pq = 0; pq < 3; ++pq) {
            const int p = (pq == 2) ? 1 : 0;
            const int q = (pq == 0) ? 1 : 2;
            const float apq = A[p][q];
            if (fabsf(apq) <= 0.0f) continue;
            const float theta = (A[q][q] - A[p][p]) / (2.0f * apq);
            const float tt = ((theta >= 0.0f) ? 1.0f : -1.0f) /
                             (fabsf(theta) + sqrtf(theta * theta + 1.0f));
            const float c = rsqrtf(tt * tt + 1.0f);
            const float s = tt * c;
            for (int k = 0; k < 3; ++k) { float a1 = A[p][k], a2 = A[q][k];
                A[p][k] = c * a1 - s * a2; A[q][k] = s * a1 + c * a2; }
            for (int k = 0; k < 3; ++k) { float a1 = A[k][p], a2 = A[k][q];
                A[k][p] = c * a1 - s * a2; A[k][q] = s * a1 + c * a2; }
            for (int k = 0; k < 3; ++k) { float v1 = V[k][p], v2 = V[k][q];
                V[k][p] = c * v1 - s * v2; V[k][q] = s * v1 + c * v2; }
        }
    }

    int id[3] = { 0, 1, 2 };
    float w[3] = { A[0][0], A[1][1], A[2][2] };
    if (w[id[0]] < w[id[1]]) { int t0 = id[0]; id[0] = id[1]; id[1] = t0; }
    if (w[id[0]] < w[id[2]]) { int t0 = id[0]; id[0] = id[2]; id[2] = t0; }
    if (w[id[1]] < w[id[2]]) { int t0 = id[1]; id[1] = id[2]; id[2] = t0; }

    float v1[3], v2[3], v3[3];
    for (int k = 0; k < 3; ++k) { v1[k] = V[k][id[0]]; v2[k] = V[k][id[1]]; v3[k] = V[k][id[2]]; }

    float u1[3], u2[3], u3[3];
    for (int i = 0; i < 3; ++i) u1[i] = H[i][0] * v1[0] + H[i][1] * v1[1] + H[i][2] * v1[2];
    {
        float n1 = u1[0]*u1[0] + u1[1]*u1[1] + u1[2]*u1[2];
        float r = (n1 > 0.0f) ? rsqrtf(n1) : 0.0f;
        u1[0] *= r; u1[1] *= r; u1[2] *= r;
    }
    for (int i = 0; i < 3; ++i) u2[i] = H[i][0] * v2[0] + H[i][1] * v2[1] + H[i][2] * v2[2];
    {
        float pr = u1[0]*u2[0] + u1[1]*u2[1] + u1[2]*u2[2];
        u2[0] -= pr * u1[0]; u2[1] -= pr * u1[1]; u2[2] -= pr * u1[2];
        float n2 = u2[0]*u2[0] + u2[1]*u2[1] + u2[2]*u2[2];
        float r = (n2 > 0.0f) ? rsqrtf(n2) : 0.0f;
        u2[0] *= r; u2[1] *= r; u2[2] *= r;
    }
    u3[0] = u1[1]*u2[2] - u1[2]*u2[1];
    u3[1] = u1[2]*u2[0] - u1[0]*u2[2];
    u3[2] = u1[0]*u2[1] - u1[1]*u2[0];

    const float d =
        v1[0] * (v2[1]*v3[2] - v2[2]*v3[1]) -
        v1[1] * (v2[0]*v3[2] - v2[2]*v3[0]) +
        v1[2] * (v2[0]*v3[1] - v2[1]*v3[0]);

    float R[9];
    for (int i = 0; i < 3; ++i)
        for (int j = 0; j < 3; ++j)
            R[3 * i + j] = v1[i]*u1[j] + v2[i]*u2[j] + d * v3[i]*u3[j];
    for (int k = 0; k < 9; ++k) Rt[k] = R[k];
    for (int i = 0; i < 3; ++i)
        Rt[9 + i] = (float)ct[i] - (R[3*i]*(float)cs[0] + R[3*i+1]*(float)cs[1]
                                    + R[3*i+2]*(float)cs[2]);
}

// ---------------------------------------------------------------------------
__device__ __forceinline__ void warp_reduce16_store(const float v[16],
                                                    int buf, int b, int row) {
    const int lane = threadIdx.x & 31;
#pragma unroll
    for (int q = 0; q < 16; ++q) {
        float r = v[q];
#pragma unroll
        for (int o = 16; o > 0; o >>= 1) r += __shfl_down_sync(0xffffffffu, r, o);
        if (lane == 0) g_wsum[buf][b][row][q] = r;
    }
}

// ---------------------------------------------------------------------------
// Per-block redundant fin (identical arithmetic to R11-R15; strided by TPB).
// ---------------------------------------------------------------------------
__device__ __forceinline__ void local_fin(int buf, int k_is0,
                                          float* part1, double (*sums)[16],
                                          float (*Rsh)[12], double* errlastS,
                                          int* convfS, int* doneS) {
    const int tid = threadIdx.x;
    for (int c = tid; c < BB * 16 * 16; c += TPB) {
        const int bb = c >> 8, rem = c & 255, qq = rem >> 4, bx = rem & 15;
        float a = 0.f;
#pragma unroll
        for (int w = 0; w < 8; ++w)
            a += g_wsum[buf][bb][bx * 8 + w][qq];
        part1[c] = a;
    }
    __syncthreads();
    if (tid < BB * 16) {
        const int bb = tid >> 4, qq = tid & 15;
        double acc = 0.0;
        for (int bx = 0; bx < 16; ++bx)
            acc += (double)part1[(bb * 16 + qq) * 16 + bx];
        sums[bb][qq] = acc;
    }
    __syncthreads();
    double errnew = 0.0;
    if (tid < BB) {
        errnew = sums[tid][15] / (double)NPTS;
        const double errlast = k_is0 ? 0.0 : errlastS[tid];
        convfS[tid] = (fabs(errnew - errlast) < ICP_TOL) ? 1 : 0;
        kabsch_sums(sums[tid], Rsh[tid]);
    }
    __syncthreads();
    if (tid == 0) {
        const int all  = convfS[0] & convfS[1] & convfS[2] & convfS[3];
        const int prev = k_is0 ? 0 : *doneS;
        *doneS = prev | all;
    }
    __syncthreads();
    if (tid < BB) {
        if (!(*doneS)) {
            errlastS[tid] = errnew;
        } else {
            for (int qq = 0; qq < 12; ++qq)
                Rsh[tid][qq] = (qq == 0 || qq == 4 || qq == 8) ? 1.f : 0.f;
        }
    }
    __syncthreads();
}

// ---------------------------------------------------------------------------
// Persistent fused ICP kernel: 128 blocks x 768 threads (1 block/SM).
// 24 warps share the 64 scan cells: warps 0-15 take 3 cells, 16-23 take 2.
// Each lane handles 4 sources; per-cell arithmetic byte-identical to R15.
// Phase A: min-VALUE-only (FMNMX). Phase B: exact index recovery by rescan.
// ---------------------------------------------------------------------------
extern __shared__ __align__(16) float smem_dyn[];

__global__ void __launch_bounds__(TPB, 1)
icp_kernel(const float* __restrict__ src, const float* __restrict__ tgt,
           float* __restrict__ out) {
    // dynamic smem layout
    float* tgP   = smem_dyn;                       // 2048 pairs * 8 f = 64KB
    float* gmins = tgP + NPAIRS * 8;               // 64 * 128 f = 32KB
    float* srcP  = gmins + NQG * SRCB;             // 128*3
    float* mw    = srcP + SRCB * 3;                // 128*3

    __shared__ float  part1[BB * 16 * 16];
    __shared__ double sums[BB][16];
    __shared__ float  Rsh[BB][12];
    __shared__ double errlastS[BB];
    __shared__ int    convfS[BB];
    __shared__ int    doneS;
    __shared__ int    s_isfin;

    const int tid  = threadIdx.x;
    const int w    = tid >> 5;                 // warp 0..23
    const int lane = tid & 31;
    const int b    = blockIdx.x >> 5;          // batch
    const int blk2 = blockIdx.x & 31;          // 128-source slice

    // cell assignment: warps 0-15 -> 3 cells, warps 16-23 -> 2 cells
    const int cbase = (w < 16) ? 3 * w : 48 + 2 * (w - 16);
    const int ncel  = (w < 16) ? 3 : 2;

    const int s0 = lane, s1 = lane + 32, s2 = lane + 64, s3 = lane + 96;

    // ---- stage full target set; pair p: [x0 x1 y0 y1 z0 z1 w0 w1]
    {
        const float* T = tgt + (size_t)b * MPTS * 3;
        for (int k = tid; k < MPTS; k += TPB) {
            float x = T[3 * k], y = T[3 * k + 1], z = T[3 * k + 2];
            float ww = fmaf(x, x, fmaf(y, y, z * z));
            int p = k >> 1, h = k & 1;
            tgP[p * 8 + 0 + h] = x;
            tgP[p * 8 + 2 + h] = y;
            tgP[p * 8 + 4 + h] = z;
            tgP[p * 8 + 6 + h] = ww;
        }
    }
    if (tid < SRCB * 3) {
        srcP[tid] = src[(size_t)(b * NPTS + blk2 * SRCB) * 3 + tid];
    }
    __syncthreads();

    const ulonglong2* tg2 = (const ulonglong2*)tgP;   // pair p = tg2[2p], tg2[2p+1]

    for (int k = 0; k < ICP_STEPS; ++k) {
        if (k > 0) {
            if (tid == 0) {
                while (*(volatile unsigned*)&g_cnt < (unsigned)(NBLK * k))
                    __nanosleep(32);
                __threadfence();
            }
            __syncthreads();
            local_fin((k - 1) & 1, (k == 1), part1, sums, Rsh, errlastS,
                      convfS, &doneS);
        }

        // ---- transform this lane's four source points (identity at k==0)
        float wx[4], wy[4], wz[4];
        {
            const int ss[4] = { s0, s1, s2, s3 };
#pragma unroll
            for (int t = 0; t < 4; ++t) {
                const float px = srcP[3 * ss[t]], py = srcP[3 * ss[t] + 1],
                            pz = srcP[3 * ss[t] + 2];
                if (k == 0) {
                    const float I[12] = {1.f,0.f,0.f, 0.f,1.f,0.f, 0.f,0.f,1.f,
                                         0.f,0.f,0.f};
                    xform(I, px, py, pz, wx[t], wy[t], wz[t]);
                } else {
                    xform(Rsh[b], px, py, pz, wx[t], wy[t], wz[t]);
                }
            }
        }

        // ================= Phase A: min-value-only scan, 4 sources ==========
        {
            unsigned long long ax[4], ay[4], az[4];
#pragma unroll
            for (int t = 0; t < 4; ++t) {
                ax[t] = pk2(-2.f * wx[t]);
                ay[t] = pk2(-2.f * wy[t]);
                az[t] = pk2(-2.f * wz[t]);
            }

            for (int g = 0; g < ncel; ++g) {
                const int cell = cbase + g;
                const int gp   = cell * GP;
                float gmE[4] = { 3.4e38f, 3.4e38f, 3.4e38f, 3.4e38f };
                float gmO[4] = { 3.4e38f, 3.4e38f, 3.4e38f, 3.4e38f };
#pragma unroll 8
                for (int i = 0; i < GP; ++i) {
                    const ulonglong2 A  = tg2[2 * (gp + i)];
                    const ulonglong2 Bv = tg2[2 * (gp + i) + 1];
#pragma unroll
                    for (int t = 0; t < 4; ++t) {
                        unsigned long long s01 =
                            fma2(ax[t], A.x, fma2(ay[t], A.y,
                                 fma2(az[t], Bv.x, Bv.y)));
                        float e, o;
                        upk2(s01, e, o);
                        gmE[t] = fminf(gmE[t], e);
                        gmO[t] = fminf(gmO[t], o);
                    }
                }
                const int coff = cell * SRCB;
                gmins[coff + s0] = fminf(gmE[0], gmO[0]);
                gmins[coff + s1] = fminf(gmE[1], gmO[1]);
                gmins[coff + s2] = fminf(gmE[2], gmO[2]);
                gmins[coff + s3] = fminf(gmE[3], gmO[3]);
            }
        }
        if (w == 0) {   // one copy of the transformed points per source
            mw[3 * s0] = wx[0]; mw[3 * s0 + 1] = wy[0]; mw[3 * s0 + 2] = wz[0];
            mw[3 * s1] = wx[1]; mw[3 * s1 + 1] = wy[1]; mw[3 * s1 + 2] = wz[1];
            mw[3 * s2] = wx[2]; mw[3 * s2 + 1] = wy[2]; mw[3 * s2 + 2] = wz[2];
            mw[3 * s3] = wx[3]; mw[3 * s3 + 1] = wy[3]; mw[3 * s3 + 2] = wz[3];
        }
        __syncthreads();

        // ============ Phase B + moments (threads 0..127, src = tid) ========
        if (tid < SRCB) {
            float m = gmins[tid];
#pragma unroll 8
            for (int t = 1; t < NQG; ++t) m = fminf(m, gmins[t * SRCB + tid]);

            int qg = 0;
#pragma unroll 8
            for (int t = NQG - 1; t >= 0; --t)
                if (gmins[t * SRCB + tid] == m) qg = t;

            const float mx = mw[3 * tid], my = mw[3 * tid + 1], mz = mw[3 * tid + 2];
            const unsigned long long ax2 = pk2(-2.f * mx);
            const unsigned long long ay2 = pk2(-2.f * my);
            const unsigned long long az2 = pk2(-2.f * mz);
            const int pstart = qg * GP;

            int jb = 0xFFFF;
#pragma unroll 4
            for (int i = 0; i < GP; ++i) {
                const ulonglong2 A  = tg2[2 * (pstart + i)];
                const ulonglong2 Bv = tg2[2 * (pstart + i) + 1];
                unsigned long long s01 =
                    fma2(ax2, A.x, fma2(ay2, A.y, fma2(az2, Bv.x, Bv.y)));
                float e, o;
                upk2(s01, e, o);
                if (e == m) jb = min(jb, 2 * (pstart + i));
                if (o == m) jb = min(jb, 2 * (pstart + i) + 1);
            }
            const unsigned j = (unsigned)jb;
            const float    s = m;

            const float a2v = fmaf(mx, mx, fmaf(my, my, mz * mz));
            const float d2  = fmaxf(s + a2v, 0.f);
            const float ec  = sqrtf(d2);

            const unsigned p = j >> 1, h = j & 1;
            const float tx = tgP[p * 8 + 0 + h];
            const float ty = tgP[p * 8 + 2 + h];
            const float tz = tgP[p * 8 + 4 + h];

            const float v[16] = { mx, my, mz, tx, ty, tz,
                                  mx * tx, mx * ty, mx * tz,
                                  my * tx, my * ty, my * tz,
                                  mz * tx, mz * ty, mz * tz, ec };
            warp_reduce16_store(v, k & 1, b, blk2 * 4 + (tid >> 5));

            srcP[3 * tid] = mx; srcP[3 * tid + 1] = my; srcP[3 * tid + 2] = mz;
        }
        __threadfence();
        __syncthreads();
        if (tid == 0) atomicAdd(&g_cnt, 1u);
    }

    // ======================= FINAL kabsch(source, temporal) =================
    if (tid == 0) {
        while (*(volatile unsigned*)&g_cnt < (unsigned)(NBLK * ICP_STEPS))
            __nanosleep(32);
        __threadfence();
    }
    __syncthreads();
    local_fin((ICP_STEPS - 1) & 1, 0, part1, sums, Rsh, errlastS, convfS, &doneS);

    if (tid < SRCB) {
        const float px = srcP[3 * tid], py = srcP[3 * tid + 1], pz = srcP[3 * tid + 2];
        float wxf, wyf, wzf;
        xform(Rsh[b], px, py, pz, wxf, wyf, wzf);

        const float sx = src[3 * (b * NPTS + blk2 * SRCB + tid)];
        const float sy = src[3 * (b * NPTS + blk2 * SRCB + tid) + 1];
        const float sz = src[3 * (b * NPTS + blk2 * SRCB + tid) + 2];

        const float v[16] = { sx, sy, sz, wxf, wyf, wzf,
                              sx * wxf, sx * wyf, sx * wzf,
                              sy * wxf, sy * wyf, sy * wzf,
                              sz * wxf, sz * wyf, sz * wzf, 0.f };
        warp_reduce16_store(v, 0, b, blk2 * 4 + (tid >> 5));   // buf 0 (16&1)
    }
    __threadfence();
    __syncthreads();
    if (tid == 0) {
        unsigned old = atomicAdd(&g_cnt, 1u);
        s_isfin = (old == (unsigned)(NBLK * (ICP_STEPS + 1) - 1)) ? 1 : 0;
    }
    __syncthreads();
    if (!s_isfin) return;

    // ---- last block: final sums + kabsch, output, counter reset
    if (tid == 0) __threadfence();
    __syncthreads();
    for (int c = tid; c < BB * 16 * 16; c += TPB) {
        const int bb = c >> 8, rem = c & 255, qq = rem >> 4, bx = rem & 15;
        float a = 0.f;
#pragma unroll
        for (int ww = 0; ww < 8; ++ww)
            a += g_wsum[0][bb][bx * 8 + ww][qq];
        part1[c] = a;
    }
    __syncthreads();
    if (tid < BB * 16) {
        const int bb = tid >> 4, qq = tid & 15;
        double acc = 0.0;
        for (int bx = 0; bx < 16; ++bx)
            acc += (double)part1[(bb * 16 + qq) * 16 + bx];
        sums[bb][qq] = acc;
    }
    __syncthreads();
    if (tid < BB) kabsch_sums(sums[tid], Rsh[tid]);
    __syncthreads();

    if (tid < BB * 12) {
        const int bb = tid / 12, qq = tid % 12;
        const int i = qq / 4, jj = qq % 4;
        float val = (jj < 3) ? Rsh[bb][3 * i + jj] : Rsh[bb][9 + i];
        out[bb * 12 + i * 4 + jj] = val;
    }

    if (tid == 0) g_cnt = 0u;
}

// ---------------------------------------------------------------------------
extern "C" void kernel_launch(void* const* d_in, const int* in_sizes, int n_in,
                              void* d_out, int out_size) {
    const float* source = (const float*)d_in[0];
    const float* target = (const float*)d_in[1];
    float*       out    = (float*)d_out;

    const int smem_bytes = (NPAIRS * 8 + NQG * SRCB + SRCB * 3 + SRCB * 3) * 4
                         + 64;

    cudaFuncSetAttribute(icp_kernel,
                         cudaFuncAttributeMaxDynamicSharedMemorySize, smem_bytes);

    icp_kernel<<<NBLK, TPB, smem_bytes>>>(source, target, out);
}

// round 17
// speedup vs baseline: 1.0419x; 1.0419x over previous
#include <cuda_runtime.h>
#include <math.h>

// Problem constants
#define BB        4
#define NPTS      4096
#define MPTS      4096
#define TPB       512
#define SRCB      128               // sources per block
#define PARTS     16                // target parts (one per warp)
#define BLK_PER_B 32                // blocks per batch
#define NBLK      (BB * BLK_PER_B)  // 128 blocks total, 1 per SM
#define NPAIRS    (MPTS / 2)        // 2048 target pairs per batch
#define PPP       (NPAIRS / PARTS)  // 128 pairs per part
#define GRPS      4                 // groups per part
#define GP        (PPP / GRPS)      // 32 pairs per group
#define NQG       (PARTS * GRPS)    // 64 cells; cell t covers pairs [32t,32t+32)
#define ICP_STEPS 16
#define ICP_TOL   1e-6

// ---------------------------------------------------------------------------
// Device-global state. g_cnt monotonic within a launch, reset by the final
// block -> replay-clean for CUDA graphs. g_wsum double-buffered by parity.
// ---------------------------------------------------------------------------
__device__ float    g_wsum[2][BB][128][16];
__device__ unsigned g_cnt;

// ---------------------------------------------------------------------------
__device__ __forceinline__ void xform(const float* Mtx,
                                      float px, float py, float pz,
                                      float& qx, float& qy, float& qz) {
    qx = fmaf(Mtx[0], px, fmaf(Mtx[1], py, fmaf(Mtx[2], pz, Mtx[9])));
    qy = fmaf(Mtx[3], px, fmaf(Mtx[4], py, fmaf(Mtx[5], pz, Mtx[10])));
    qz = fmaf(Mtx[6], px, fmaf(Mtx[7], py, fmaf(Mtx[8], pz, Mtx[11])));
}

// packed f32x2 helpers (per-half rounding identical to scalar FFMA)
__device__ __forceinline__ unsigned long long pk2(float v) {
    unsigned long long r;
    asm("mov.b64 %0, {%1, %1};" : "=l"(r) : "f"(v));
    return r;
}
__device__ __forceinline__ unsigned long long fma2(unsigned long long a,
                                                   unsigned long long b,
                                                   unsigned long long c) {
    unsigned long long d;
    asm("fma.rn.f32x2 %0, %1, %2, %3;" : "=l"(d) : "l"(a), "l"(b), "l"(c));
    return d;
}
__device__ __forceinline__ void upk2(unsigned long long v, float& lo, float& hi) {
    asm("mov.b64 {%0, %1}, %2;" : "=f"(lo), "=f"(hi) : "l"(v));
}

// ---------------------------------------------------------------------------
// Kabsch from accumulated sums (identical arithmetic to R2-R16).
// ---------------------------------------------------------------------------
__device__ void kabsch_sums(const double* S, float* Rt) {
    const double invN = 1.0 / (double)NPTS;
    double cs[3] = { S[0] * invN, S[1] * invN, S[2] * invN };
    double ct[3] = { S[3] * invN, S[4] * invN, S[5] * invN };

    float H[3][3];
    for (int i = 0; i < 3; ++i)
        for (int j = 0; j < 3; ++j)
            H[i][j] = (float)(S[6 + 3 * i + j] - (double)NPTS * cs[i] * ct[j]);

    float A[3][3];
    for (int i = 0; i < 3; ++i)
        for (int j = 0; j < 3; ++j)
            A[i][j] = H[0][i] * H[0][j] + H[1][i] * H[1][j] + H[2][i] * H[2][j];

    float V[3][3] = { {1,0,0},{0,1,0},{0,0,1} };
    const float diagmag = fabsf(A[0][0]) + fabsf(A[1][1]) + fabsf(A[2][2]);
    const float offeps  = diagmag * 1e-9f;
    for (int sweep = 0; sweep < 8; ++sweep) {
        const float off = fabsf(A[0][1]) + fabsf(A[0][2]) + fabsf(A[1][2]);
        if (off <= offeps) break;
        for (int pq = 0; pq < 3; ++pq) {
            const int p = (pq == 2) ? 1 : 0;
            const int q = (pq == 0) ? 1 : 2;
            const float apq = A[p][q];
            if (fabsf(apq) <= 0.0f) continue;
            const float theta = (A[q][q] - A[p][p]) / (2.0f * apq);
            const float tt = ((theta >= 0.0f) ? 1.0f : -1.0f) /
                             (fabsf(theta) + sqrtf(theta * theta + 1.0f));
            const float c = rsqrtf(tt * tt + 1.0f);
            const float s = tt * c;
            for (int k = 0; k < 3; ++k) { float a1 = A[p][k], a2 = A[q][k];
                A[p][k] = c * a1 - s * a2; A[q][k] = s * a1 + c * a2; }
            for (int k = 0; k < 3; ++k) { float a1 = A[k][p], a2 = A[k][q];
                A[k][p] = c * a1 - s * a2; A[k][q] = s * a1 + c * a2; }
            for (int k = 0; k < 3; ++k) { float v1 = V[k][p], v2 = V[k][q];
                V[k][p] = c * v1 - s * v2; V[k][q] = s * v1 + c * v2; }
        }
    }

    int id[3] = { 0, 1, 2 };
    float w[3] = { A[0][0], A[1][1], A[2][2] };
    if (w[id[0]] < w[id[1]]) { int t0 = id[0]; id[0] = id[1]; id[1] = t0; }
    if (w[id[0]] < w[id[2]]) { int t0 = id[0]; id[0] = id[2]; id[2] = t0; }
    if (w[id[1]] < w[id[2]]) { int t0 = id[1]; id[1] = id[2]; id[2] = t0; }

    float v1[3], v2[3], v3[3];
    for (int k = 0; k < 3; ++k) { v1[k] = V[k][id[0]]; v2[k] = V[k][id[1]]; v3[k] = V[k][id[2]]; }

    float u1[3], u2[3], u3[3];
    for (int i = 0; i < 3; ++i) u1[i] = H[i][0] * v1[0] + H[i][1] * v1[1] + H[i][2] * v1[2];
    {
        float n1 = u1[0]*u1[0] + u1[1]*u1[1] + u1[2]*u1[2];
        float r = (n1 > 0.0f) ? rsqrtf(n1) : 0.0f;
        u1[0] *= r; u1[1] *= r; u1[2] *= r;
    }
    for (int i = 0; i < 3; ++i) u2[i] = H[i][0] * v2[0] + H[i][1] * v2[1] + H[i][2] * v2[2];
    {
        float pr = u1[0]*u2[0] + u1[1]*u2[1] + u1[2]*u2[2];
        u2[0] -= pr * u1[0]; u2[1] -= pr * u1[1]; u2[2] -= pr * u1[2];
        float n2 = u2[0]*u2[0] + u2[1]*u2[1] + u2[2]*u2[2];
        float r = (n2 > 0.0f) ? rsqrtf(n2) : 0.0f;
        u2[0] *= r; u2[1] *= r; u2[2] *= r;
    }
    u3[0] = u1[1]*u2[2] - u1[2]*u2[1];
    u3[1] = u1[2]*u2[0] - u1[0]*u2[2];
    u3[2] = u1[0]*u2[1] - u1[1]*u2[0];

    const float d =
        v1[0] * (v2[1]*v3[2] - v2[2]*v3[1]) -
        v1[1] * (v2[0]*v3[2] - v2[2]*v3[0]) +
        v1[2] * (v2[0]*v3[1] - v2[1]*v3[0]);

    float R[9];
    for (int i = 0; i < 3; ++i)
        for (int j = 0; j < 3; ++j)
            R[3 * i + j] = v1[i]*u1[j] + v2[i]*u2[j] + d * v3[i]*u3[j];
    for (int k = 0; k < 9; ++k) Rt[k] = R[k];
    for (int i = 0; i < 3; ++i)
        Rt[9 + i] = (float)ct[i] - (R[3*i]*(float)cs[0] + R[3*i+1]*(float)cs[1]
                                    + R[3*i+2]*(float)cs[2]);
}

// ---------------------------------------------------------------------------
__device__ __forceinline__ void warp_reduce16_store(const float v[16],
                                                    int buf, int b, int row) {
    const int lane = threadIdx.x & 31;
#pragma unroll
    for (int q = 0; q < 16; ++q) {
        float r = v[q];
#pragma unroll
        for (int o = 16; o > 0; o >>= 1) r += __shfl_down_sync(0xffffffffu, r, o);
        if (lane == 0) g_wsum[buf][b][row][q] = r;
    }
}

// ---------------------------------------------------------------------------
// Per-block redundant fin (identical to R11-R16).
// ---------------------------------------------------------------------------
__device__ __forceinline__ void local_fin(int buf, int k_is0,
                                          float* part1, double (*sums)[16],
                                          float (*Rsh)[12], double* errlastS,
                                          int* convfS, int* doneS) {
    const int tid = threadIdx.x;
    for (int c = tid; c < BB * 16 * 16; c += TPB) {
        const int bb = c >> 8, rem = c & 255, qq = rem >> 4, bx = rem & 15;
        float a = 0.f;
#pragma unroll
        for (int w = 0; w < 8; ++w)
            a += g_wsum[buf][bb][bx * 8 + w][qq];
        part1[c] = a;
    }
    __syncthreads();
    if (tid < BB * 16) {
        const int bb = tid >> 4, qq = tid & 15;
        double acc = 0.0;
        for (int bx = 0; bx < 16; ++bx)
            acc += (double)part1[(bb * 16 + qq) * 16 + bx];
        sums[bb][qq] = acc;
    }
    __syncthreads();
    double errnew = 0.0;
    if (tid < BB) {
        errnew = sums[tid][15] / (double)NPTS;
        const double errlast = k_is0 ? 0.0 : errlastS[tid];
        convfS[tid] = (fabs(errnew - errlast) < ICP_TOL) ? 1 : 0;
        kabsch_sums(sums[tid], Rsh[tid]);
    }
    __syncthreads();
    if (tid == 0) {
        const int all  = convfS[0] & convfS[1] & convfS[2] & convfS[3];
        const int prev = k_is0 ? 0 : *doneS;
        *doneS = prev | all;
    }
    __syncthreads();
    if (tid < BB) {
        if (!(*doneS)) {
            errlastS[tid] = errnew;
        } else {
            for (int qq = 0; qq < 12; ++qq)
                Rsh[tid][qq] = (qq == 0 || qq == 4 || qq == 8) ? 1.f : 0.f;
        }
    }
    __syncthreads();
}

// ---------------------------------------------------------------------------
// Persistent fused ICP kernel: 128 blocks x 512 threads (1 block/SM).
// Warp w = target part (16 x 128 pairs); each lane handles 4 sources.
// Phase A: min-VALUE-only (FMNMX), group loop unrolled 8 (R15 champion).
// Phase B: m/qg search parallelized 4 threads/source (exact shfl-min merge),
//          then exact index recovery by rescan on threads 0..127.
// ---------------------------------------------------------------------------
extern __shared__ __align__(16) float smem_dyn[];

__global__ void __launch_bounds__(TPB, 1)
icp_kernel(const float* __restrict__ src, const float* __restrict__ tgt,
           float* __restrict__ out) {
    // dynamic smem layout
    float* tgP   = smem_dyn;                       // 2048 pairs * 8 f = 64KB
    float* gmins = tgP + NPAIRS * 8;               // 64 * 128 f = 32KB
    float* srcP  = gmins + NQG * SRCB;             // 128*3
    float* mw    = srcP + SRCB * 3;                // 128*3

    __shared__ float  part1[BB * 16 * 16];
    __shared__ double sums[BB][16];
    __shared__ float  Rsh[BB][12];
    __shared__ double errlastS[BB];
    __shared__ int    convfS[BB];
    __shared__ float  mS[SRCB];
    __shared__ int    qgS[SRCB];
    __shared__ int    doneS;
    __shared__ int    s_isfin;

    const int tid  = threadIdx.x;
    const int w    = tid >> 5;                 // warp 0..15 == target part
    const int lane = tid & 31;
    const int b    = blockIdx.x >> 5;          // batch
    const int blk2 = blockIdx.x & 31;          // 128-source slice

    const int s0 = lane, s1 = lane + 32, s2 = lane + 64, s3 = lane + 96;

    // ---- stage full target set; pair p: [x0 x1 y0 y1 z0 z1 w0 w1]
    {
        const float* T = tgt + (size_t)b * MPTS * 3;
        for (int k = tid; k < MPTS; k += TPB) {
            float x = T[3 * k], y = T[3 * k + 1], z = T[3 * k + 2];
            float ww = fmaf(x, x, fmaf(y, y, z * z));
            int p = k >> 1, h = k & 1;
            tgP[p * 8 + 0 + h] = x;
            tgP[p * 8 + 2 + h] = y;
            tgP[p * 8 + 4 + h] = z;
            tgP[p * 8 + 6 + h] = ww;
        }
    }
    if (tid < SRCB * 3) {
        srcP[tid] = src[(size_t)(b * NPTS + blk2 * SRCB) * 3 + tid];
    }
    __syncthreads();

    const ulonglong2* tg2 = (const ulonglong2*)tgP;   // pair p = tg2[2p], tg2[2p+1]

    for (int k = 0; k < ICP_STEPS; ++k) {
        if (k > 0) {
            if (tid == 0) {
                while (*(volatile unsigned*)&g_cnt < (unsigned)(NBLK * k))
                    __nanosleep(32);
                __threadfence();
            }
            __syncthreads();
            local_fin((k - 1) & 1, (k == 1), part1, sums, Rsh, errlastS,
                      convfS, &doneS);
        }

        // ---- transform this lane's four source points (identity at k==0)
        float wx[4], wy[4], wz[4];
        {
            const int ss[4] = { s0, s1, s2, s3 };
#pragma unroll
            for (int t = 0; t < 4; ++t) {
                const float px = srcP[3 * ss[t]], py = srcP[3 * ss[t] + 1],
                            pz = srcP[3 * ss[t] + 2];
                if (k == 0) {
                    const float I[12] = {1.f,0.f,0.f, 0.f,1.f,0.f, 0.f,0.f,1.f,
                                         0.f,0.f,0.f};
                    xform(I, px, py, pz, wx[t], wy[t], wz[t]);
                } else {
                    xform(Rsh[b], px, py, pz, wx[t], wy[t], wz[t]);
                }
            }
        }

        // ================= Phase A: min-value-only scan, 4 sources ==========
        {
            unsigned long long ax[4], ay[4], az[4];
#pragma unroll
            for (int t = 0; t < 4; ++t) {
                ax[t] = pk2(-2.f * wx[t]);
                ay[t] = pk2(-2.f * wy[t]);
                az[t] = pk2(-2.f * wz[t]);
            }
            const int pbase = w * PPP;

#pragma unroll
            for (int grp = 0; grp < GRPS; ++grp) {
                const int gp = pbase + grp * GP;
                float gmE[4] = { 3.4e38f, 3.4e38f, 3.4e38f, 3.4e38f };
                float gmO[4] = { 3.4e38f, 3.4e38f, 3.4e38f, 3.4e38f };
#pragma unroll 8
                for (int i = 0; i < GP; ++i) {
                    const ulonglong2 A  = tg2[2 * (gp + i)];
                    const ulonglong2 Bv = tg2[2 * (gp + i) + 1];
#pragma unroll
                    for (int t = 0; t < 4; ++t) {
                        unsigned long long s01 =
                            fma2(ax[t], A.x, fma2(ay[t], A.y,
                                 fma2(az[t], Bv.x, Bv.y)));
                        float e, o;
                        upk2(s01, e, o);
                        gmE[t] = fminf(gmE[t], e);
                        gmO[t] = fminf(gmO[t], o);
                    }
                }
                const int cell = (w * GRPS + grp) * SRCB;
                gmins[cell + s0] = fminf(gmE[0], gmO[0]);
                gmins[cell + s1] = fminf(gmE[1], gmO[1]);
                gmins[cell + s2] = fminf(gmE[2], gmO[2]);
                gmins[cell + s3] = fminf(gmE[3], gmO[3]);
            }
        }
        if (w == 0) {   // one copy of the transformed points per source
            mw[3 * s0] = wx[0]; mw[3 * s0 + 1] = wy[0]; mw[3 * s0 + 2] = wz[0];
            mw[3 * s1] = wx[1]; mw[3 * s1 + 1] = wy[1]; mw[3 * s1 + 2] = wz[1];
            mw[3 * s2] = wx[2]; mw[3 * s2 + 1] = wy[2]; mw[3 * s2 + 2] = wz[2];
            mw[3 * s3] = wx[3]; mw[3 * s3 + 1] = wy[3]; mw[3 * s3 + 2] = wz[3];
        }
        __syncthreads();

        // ===== Phase B part 1: m & first-cell search, 4 threads per source ==
        {
            const int srcq = tid >> 2;        // 0..127
            const int sub  = tid & 3;         // cell range [sub*16, sub*16+16)
            float mloc = gmins[(sub * 16) * SRCB + srcq];
#pragma unroll
            for (int t = 1; t < 16; ++t)
                mloc = fminf(mloc, gmins[(sub * 16 + t) * SRCB + srcq]);
            // exact global min (min is associative/commutative)
            mloc = fminf(mloc, __shfl_xor_sync(0xffffffffu, mloc, 1));
            mloc = fminf(mloc, __shfl_xor_sync(0xffffffffu, mloc, 2));

            // first cell (ascending) attaining m within this sub-range
            int qloc = 1 << 20;
#pragma unroll
            for (int t = 15; t >= 0; --t)
                if (gmins[(sub * 16 + t) * SRCB + srcq] == mloc)
                    qloc = sub * 16 + t;
            qloc = min(qloc, __shfl_xor_sync(0xffffffffu, qloc, 1));
            qloc = min(qloc, __shfl_xor_sync(0xffffffffu, qloc, 2));

            if (sub == 0) { mS[srcq] = mloc; qgS[srcq] = qloc; }
        }
        __syncthreads();

        // ===== Phase B part 2 + moments (threads 0..127, src = tid) ========
        if (tid < SRCB) {
            const float m  = mS[tid];
            const int   qg = qgS[tid];

            const float mx = mw[3 * tid], my = mw[3 * tid + 1], mz = mw[3 * tid + 2];
            const unsigned long long ax2 = pk2(-2.f * mx);
            const unsigned long long ay2 = pk2(-2.f * my);
            const unsigned long long az2 = pk2(-2.f * mz);
            const int pstart = qg * GP;

            int jb = 0xFFFF;
#pragma unroll 4
            for (int i = 0; i < GP; ++i) {
                const ulonglong2 A  = tg2[2 * (pstart + i)];
                const ulonglong2 Bv = tg2[2 * (pstart + i) + 1];
                unsigned long long s01 =
                    fma2(ax2, A.x, fma2(ay2, A.y, fma2(az2, Bv.x, Bv.y)));
                float e, o;
                upk2(s01, e, o);
                if (e == m) jb = min(jb, 2 * (pstart + i));
                if (o == m) jb = min(jb, 2 * (pstart + i) + 1);
            }
            const unsigned j = (unsigned)jb;
            const float    s = m;

            const float a2v = fmaf(mx, mx, fmaf(my, my, mz * mz));
            const float d2  = fmaxf(s + a2v, 0.f);
            const float ec  = sqrtf(d2);

            const unsigned p = j >> 1, h = j & 1;
            const float tx = tgP[p * 8 + 0 + h];
            const float ty = tgP[p * 8 + 2 + h];
            const float tz = tgP[p * 8 + 4 + h];

            const float v[16] = { mx, my, mz, tx, ty, tz,
                                  mx * tx, mx * ty, mx * tz,
                                  my * tx, my * ty, my * tz,
                                  mz * tx, mz * ty, mz * tz, ec };
            warp_reduce16_store(v, k & 1, b, blk2 * 4 + (tid >> 5));

            srcP[3 * tid] = mx; srcP[3 * tid + 1] = my; srcP[3 * tid + 2] = mz;
        }
        __threadfence();
        __syncthreads();
        if (tid == 0) atomicAdd(&g_cnt, 1u);
    }

    // ======================= FINAL kabsch(source, temporal) =================
    if (tid == 0) {
        while (*(volatile unsigned*)&g_cnt < (unsigned)(NBLK * ICP_STEPS))
            __nanosleep(32);
        __threadfence();
    }
    __syncthreads();
    local_fin((ICP_STEPS - 1) & 1, 0, part1, sums, Rsh, errlastS, convfS, &doneS);

    if (tid < SRCB) {
        const float px = srcP[3 * tid], py = srcP[3 * tid + 1], pz = srcP[3 * tid + 2];
        float wxf, wyf, wzf;
        xform(Rsh[b], px, py, pz, wxf, wyf, wzf);

        const float sx = src[3 * (b * NPTS + blk2 * SRCB + tid)];
        const float sy = src[3 * (b * NPTS + blk2 * SRCB + tid) + 1];
        const float sz = src[3 * (b * NPTS + blk2 * SRCB + tid) + 2];

        const float v[16] = { sx, sy, sz, wxf, wyf, wzf,
                              sx * wxf, sx * wyf, sx * wzf,
                              sy * wxf, sy * wyf, sy * wzf,
                              sz * wxf, sz * wyf, sz * wzf, 0.f };
        warp_reduce16_store(v, 0, b, blk2 * 4 + (tid >> 5));   // buf 0 (16&1)
    }
    __threadfence();
    __syncthreads();
    if (tid == 0) {
        unsigned old = atomicAdd(&g_cnt, 1u);
        s_isfin = (old == (unsigned)(NBLK * (ICP_STEPS + 1) - 1)) ? 1 : 0;
    }
    __syncthreads();
    if (!s_isfin) return;

    // ---- last block: final sums + kabsch, output, counter reset
    if (tid == 0) __threadfence();
    __syncthreads();
    for (int c = tid; c < BB * 16 * 16; c += TPB) {
        const int bb = c >> 8, rem = c & 255, qq = rem >> 4, bx = rem & 15;
        float a = 0.f;
#pragma unroll
        for (int ww = 0; ww < 8; ++ww)
            a += g_wsum[0][bb][bx * 8 + ww][qq];
        part1[c] = a;
    }
    __syncthreads();
    if (tid < BB * 16) {
        const int bb = tid >> 4, qq = tid & 15;
        double acc = 0.0;
        for (int bx = 0; bx < 16; ++bx)
            acc += (double)part1[(bb * 16 + qq) * 16 + bx];
        sums[bb][qq] = acc;
    }
    __syncthreads();
    if (tid < BB) kabsch_sums(sums[tid], Rsh[tid]);
    __syncthreads();

    if (tid < BB * 12) {
        const int bb = tid / 12, qq = tid % 12;
        const int i = qq / 4, jj = qq % 4;
        float val = (jj < 3) ? Rsh[bb][3 * i + jj] : Rsh[bb][9 + i];
        out[bb * 12 + i * 4 + jj] = val;
    }

    if (tid == 0) g_cnt = 0u;
}

// ---------------------------------------------------------------------------
extern "C" void kernel_launch(void* const* d_in, const int* in_sizes, int n_in,
                              void* d_out, int out_size) {
    const float* source = (const float*)d_in[0];
    const float* target = (const float*)d_in[1];
    float*       out    = (float*)d_out;

    const int smem_bytes = (NPAIRS * 8 + NQG * SRCB + SRCB * 3 + SRCB * 3) * 4
                         + 64;

    cudaFuncSetAttribute(icp_kernel,
                         cudaFuncAttributeMaxDynamicSharedMemorySize, smem_bytes);

    icp_kernel<<<NBLK, TPB, smem_bytes>>>(source, target, out);
}